// round 14
// baseline (speedup 1.0000x reference)
#include <cuda_runtime.h>
#include <cuda_fp16.h>
#include <mma.h>
#include <math.h>
#include <cstdint>

using namespace nvcuda;

#define T_    4096
#define DIM   2048
#define HID   1024
#define NE    8
#define NG    9
#define SHB   8192
#define NPAIR 12288

#define BK    64
#define LDH   72     // smem stride in halves (144B) for BK=64
#define ASTG  18432  // A stage bytes  (128*72*2)
#define BSTG  18432  // B stage bytes  (128*72*2)
#define LDC   68     // GEMM1 epilogue C stride (floats)
#define LDC2  132    // GEMM2 epilogue C stride (floats)

struct Pair { int tok; int slot; float score; int pad; };

__device__ int   g_fill[NE];
__device__ int   g_off[NG + 1];
__device__ int   g_cnt[NG];
__device__ __align__(16) Pair g_pairs[NPAIR];
__device__ int   g_topk_idx[T_][2];
__device__ float g_topk_sc[T_][2];

__device__ __align__(128) __half g_xh[(size_t)T_ * DIM];
__device__ __align__(128) __half c_w1h[(size_t)NE * HID * DIM];
__device__ __align__(128) __half c_w3h[(size_t)NE * HID * DIM];
__device__ __align__(128) __half c_w2h[(size_t)NE * DIM * HID];
__device__ __align__(128) __half c_ws1h[(size_t)HID * DIM];
__device__ __align__(128) __half c_ws3h[(size_t)HID * DIM];
__device__ __align__(128) __half c_ws2h[(size_t)DIM * HID];
__device__ __align__(128) __half g_hh[(size_t)NPAIR * HID];
__device__ __align__(128) float  g_r0[(size_t)T_ * DIM];
__device__ __align__(128) float  g_r1[(size_t)T_ * DIM];

// ---------------- helpers ----------------
__device__ __forceinline__ void cp16(uint32_t dst, const void* src, int sz) {
    asm volatile("cp.async.cg.shared.global [%0], [%1], 16, %2;\n" :: "r"(dst), "l"(src), "r"(sz));
}
__device__ __forceinline__ void cp16f(uint32_t dst, const void* src) {
    asm volatile("cp.async.cg.shared.global [%0], [%1], 16;\n" :: "r"(dst), "l"(src));
}
__device__ __forceinline__ void cp_commit() { asm volatile("cp.async.commit_group;\n"); }
template<int N> __device__ __forceinline__ void cp_wait() {
    asm volatile("cp.async.wait_group %0;\n" :: "n"(N));
}

// ---------------- small kernels ----------------
__global__ void k_router(const float* __restrict__ x, const float* __restrict__ gw) {
    int warp = (blockIdx.x * blockDim.x + threadIdx.x) >> 5;
    int lane = threadIdx.x & 31;
    if (warp >= T_) return;
    const float* xr = x + (size_t)warp * DIM;
    float acc[NE];
#pragma unroll
    for (int e = 0; e < NE; e++) acc[e] = 0.f;
    for (int k = lane; k < DIM; k += 32) {
        float xv = xr[k];
#pragma unroll
        for (int e = 0; e < NE; e++) acc[e] += xv * gw[e * DIM + k];
    }
#pragma unroll
    for (int e = 0; e < NE; e++)
#pragma unroll
        for (int o = 16; o > 0; o >>= 1) acc[e] += __shfl_xor_sync(0xffffffffu, acc[e], o);
    if (lane == 0) {
        int i0 = 0; float v0 = acc[0];
#pragma unroll
        for (int e = 1; e < NE; e++) if (acc[e] > v0) { v0 = acc[e]; i0 = e; }
        int i1 = -1; float v1 = -1e30f;
#pragma unroll
        for (int e = 0; e < NE; e++) if (e != i0 && acc[e] > v1) { v1 = acc[e]; i1 = e; }
        g_topk_idx[warp][0] = i0; g_topk_idx[warp][1] = i1;
        g_topk_sc[warp][0] = 1.f / (1.f + expf(-v0));
        g_topk_sc[warp][1] = 1.f / (1.f + expf(-v1));
    }
}

// counts + offsets + zero g_fill in one small kernel
__global__ void k_scan() {
    __shared__ int sc[NE];
    int tid = threadIdx.x;
    if (tid < NE) sc[tid] = 0;
    __syncthreads();
    for (int t = tid; t < T_; t += 256) {
        atomicAdd(&sc[g_topk_idx[t][0]], 1);
        atomicAdd(&sc[g_topk_idx[t][1]], 1);
    }
    __syncthreads();
    if (tid == 0) {
        int o = 0;
        for (int e = 0; e < NE; e++) { g_off[e] = o; g_cnt[e] = sc[e]; o += sc[e]; }
        g_off[NE] = SHB; g_cnt[NE] = T_;
    }
    if (tid < NE) g_fill[tid] = 0;
}

__global__ void k_fill() {
    int t = blockIdx.x * blockDim.x + threadIdx.x;
    if (t >= T_) return;
#pragma unroll
    for (int k = 0; k < 2; k++) {
        int e = g_topk_idx[t][k];
        int pos = atomicAdd(&g_fill[e], 1);
        Pair p; p.tok = t; p.slot = k; p.score = g_topk_sc[t][k]; p.pad = 0;
        g_pairs[g_off[e] + pos] = p;
    }
    Pair ps; ps.tok = t; ps.slot = 2; ps.score = 1.f; ps.pad = 0;
    g_pairs[SHB + t] = ps;
}

// ---- single fused fp32->fp16 conversion (x + all 6 weights), ILP=4 ----
#define XF4    (T_ * DIM / 4)          // 2097152
#define BIG4   (NE * HID * DIM / 4)    // 4194304
#define SMALL4 (HID * DIM / 4)         // 524288
#define TOT4   (XF4 + 3 * BIG4 + 3 * SMALL4)   // 16252928
#define CVT_ILP 4

__global__ void k_cvt_all(const float* __restrict__ x,
                          const float* __restrict__ w1, const float* __restrict__ w3,
                          const float* __restrict__ w2, const float* __restrict__ ws1,
                          const float* __restrict__ ws3, const float* __restrict__ ws2) {
    long long base = ((long long)blockIdx.x * blockDim.x + threadIdx.x) * CVT_ILP;
    if (base >= (long long)TOT4) return;
    const float* src; __half* dst; long long o;
    long long b = base;
    if      (b < (long long)XF4)                       { src = x;   dst = g_xh;   o = b; }
    else if ((b -= XF4) < (long long)BIG4)             { src = w1;  dst = c_w1h;  o = b; }
    else if ((b -= BIG4) < (long long)BIG4)            { src = w3;  dst = c_w3h;  o = b; }
    else if ((b -= BIG4) < (long long)BIG4)            { src = w2;  dst = c_w2h;  o = b; }
    else if ((b -= BIG4) < (long long)SMALL4)          { src = ws1; dst = c_ws1h; o = b; }
    else if ((b -= SMALL4) < (long long)SMALL4)        { src = ws3; dst = c_ws3h; o = b; }
    else                                               { src = ws2; dst = c_ws2h; o = b - SMALL4; }
    float4 v[CVT_ILP];
#pragma unroll
    for (int j = 0; j < CVT_ILP; j++) v[j] = ((const float4*)src)[o + j];
#pragma unroll
    for (int j = 0; j < CVT_ILP; j++) {
        ((__half2*)dst)[(o + j) * 2]     = __floats2half2_rn(v[j].x, v[j].y);
        ((__half2*)dst)[(o + j) * 2 + 1] = __floats2half2_rn(v[j].z, v[j].w);
    }
}

// ---------------------------------------------------------------------------
// GEMM1: fp16 wmma, M=128, concat N=128 (64 w1 + 64 w3), BK=64.
// 8 warps 2x4; warp tile 64x32. 3-stage ring, 1 sync/stage (R10 order).
// ---------------------------------------------------------------------------
__global__ void __launch_bounds__(256, 2) k_gemm1() {
    int g = blockIdx.z;
    int cnt = g_cnt[g];
    int m0 = blockIdx.x * 128;
    if (m0 >= cnt) return;
    int off = g_off[g];
    int n0 = blockIdx.y * 64;
    const __half* B1 = (g < NE) ? c_w1h + (size_t)g * HID * DIM : c_ws1h;
    const __half* B3 = (g < NE) ? c_w3h + (size_t)g * HID * DIM : c_ws3h;

    extern __shared__ __align__(16) char dsm[];
    __half* As = (__half*)dsm;                 // 3 * 18432 B
    __half* Bs = (__half*)(dsm + 3 * ASTG);    // 3 * 18432 B
    __shared__ int   s_tok[128];
    __shared__ float s_sc[128];

    int tid = threadIdx.x, warp = tid >> 5;
    int wm = warp >> 2, wn = warp & 3;
    if (tid < 128) {
        int mi = m0 + tid;
        if (mi < cnt) { Pair p = g_pairs[off + mi]; s_tok[tid] = p.tok; s_sc[tid] = p.score; }
        else          { s_tok[tid] = -1; s_sc[tid] = 0.f; }
    }
    __syncthreads();

    uint32_t asb = (uint32_t)__cvta_generic_to_shared(As);
    uint32_t bsb = (uint32_t)__cvta_generic_to_shared(Bs);

    wmma::fragment<wmma::accumulator, 16, 16, 16, float> acc[4][2];
#pragma unroll
    for (int i = 0; i < 4; i++)
#pragma unroll
        for (int j = 0; j < 2; j++) wmma::fill_fragment(acc[i][j], 0.f);

    auto ldst = [&](int s, int b) {
        int k0 = s * BK;
#pragma unroll
        for (int i = 0; i < 4; i++) {                 // A: 128 rows x 8 chunks
            int idx = tid + (i << 8);
            int row = idx >> 3, c = idx & 7;
            int tok = s_tok[row];
            cp16(asb + b * ASTG + (uint32_t)(row * LDH + c * 8) * 2,
                 g_xh + (size_t)(tok < 0 ? 0 : tok) * DIM + k0 + c * 8,
                 tok < 0 ? 0 : 16);
        }
#pragma unroll
        for (int i = 0; i < 4; i++) {                 // B concat: rows 0-63 w1, 64-127 w3
            int idx = tid + (i << 8);
            int row = idx >> 3, c = idx & 7;
            const __half* src = (row < 64)
                ? B1 + (size_t)(n0 + row) * DIM + k0 + c * 8
                : B3 + (size_t)(n0 + row - 64) * DIM + k0 + c * 8;
            cp16f(bsb + b * BSTG + (uint32_t)(row * LDH + c * 8) * 2, src);
        }
        cp_commit();
    };

    auto compute = [&](int b) {
#pragma unroll
        for (int kk = 0; kk < 4; kk++) {
            wmma::fragment<wmma::matrix_a, 16, 16, 16, __half, wmma::row_major> af[4];
            wmma::fragment<wmma::matrix_b, 16, 16, 16, __half, wmma::col_major> bf[2];
#pragma unroll
            for (int i = 0; i < 4; i++)
                wmma::load_matrix_sync(af[i], &As[b * (ASTG / 2) + (wm * 64 + i * 16) * LDH + kk * 16], LDH);
#pragma unroll
            for (int j = 0; j < 2; j++)
                wmma::load_matrix_sync(bf[j], &Bs[b * (BSTG / 2) + (wn * 32 + j * 16) * LDH + kk * 16], LDH);
#pragma unroll
            for (int i = 0; i < 4; i++)
#pragma unroll
                for (int j = 0; j < 2; j++)
                    wmma::mma_sync(acc[i][j], af[i], bf[j], acc[i][j]);
        }
    };

    const int NS = DIM / BK;   // 32
    ldst(0, 0); ldst(1, 1);
    for (int s = 0; s < NS; s++) {
        if (s + 1 < NS) cp_wait<1>(); else cp_wait<0>();
        __syncthreads();
        compute(s % 3);
        if (s + 2 < NS) ldst(s + 2, (s + 2) % 3);
    }
    __syncthreads();   // pipeline smem quiesced before epilogue reuse

    // epilogue: C1 (p1) / C3 (p3) to smem, SwiGLU + score, store half
    float* C1 = (float*)dsm;
    float* C3 = (float*)dsm + 128 * LDC;
    float* Cd = (wn < 2) ? C1 : C3;
    int cc = (wn & 1) * 32;
#pragma unroll
    for (int i = 0; i < 4; i++)
#pragma unroll
        for (int j = 0; j < 2; j++)
            wmma::store_matrix_sync(&Cd[(wm * 64 + i * 16) * LDC + cc + j * 16],
                                    acc[i][j], LDC, wmma::mem_row_major);
    __syncthreads();
#pragma unroll
    for (int i = 0; i < 8; i++) {                    // 128 rows x 16 float4
        int idx = tid + (i << 8);
        int row = idx >> 4, c4 = idx & 15;
        if (m0 + row < cnt) {
            float sc = s_sc[row];
            float4 v1 = *(float4*)&C1[row * LDC + c4 * 4];
            float4 v3 = *(float4*)&C3[row * LDC + c4 * 4];
            float o0, o1, o2, o3, p1, p3;
            p1 = v1.x * sc; p3 = v3.x * sc; o0 = p1 * (1.f / (1.f + __expf(-p1))) * p3;
            p1 = v1.y * sc; p3 = v3.y * sc; o1 = p1 * (1.f / (1.f + __expf(-p1))) * p3;
            p1 = v1.z * sc; p3 = v3.z * sc; o2 = p1 * (1.f / (1.f + __expf(-p1))) * p3;
            p1 = v1.w * sc; p3 = v3.w * sc; o3 = p1 * (1.f / (1.f + __expf(-p1))) * p3;
            __half* hdst = g_hh + (size_t)(off + m0 + row) * HID + n0 + c4 * 4;
            *(__half2*)(hdst)     = __floats2half2_rn(o0, o1);
            *(__half2*)(hdst + 2) = __floats2half2_rn(o2, o3);
        }
    }
}

// ---------------------------------------------------------------------------
// GEMM2: fp16 wmma, M=128, N=128, K=HID, BK=64. 3-stage ring (R10 order).
// All 9 groups in one grid; slot0->g_r0, slot1->g_r1, shared->out.
// ---------------------------------------------------------------------------
__global__ void __launch_bounds__(256, 2) k_gemm2(float* __restrict__ out) {
    int g = blockIdx.z;
    int cnt = g_cnt[g];
    int m0 = blockIdx.x * 128;
    if (m0 >= cnt) return;
    int off = g_off[g];
    int n0 = blockIdx.y * 128;
    const __half* B = (g < NE) ? c_w2h + (size_t)g * DIM * HID : c_ws2h;
    const __half* A = g_hh + (size_t)(off + m0) * HID;
    int mrem = cnt - m0;

    extern __shared__ __align__(16) char dsm[];
    __half* As = (__half*)dsm;                 // 3 * 18432 B
    __half* Bs = (__half*)(dsm + 3 * ASTG);    // 3 * 18432 B
    __shared__ int s_tok[128];
    __shared__ int s_slot[128];

    int tid = threadIdx.x, warp = tid >> 5;
    int wm = warp >> 2, wn = warp & 3;
    if (tid < 128) {
        int mi = m0 + tid;
        if (mi < cnt) { Pair p = g_pairs[off + mi]; s_tok[tid] = p.tok; s_slot[tid] = p.slot; }
        else          { s_tok[tid] = 0; s_slot[tid] = -1; }
    }
    __syncthreads();

    uint32_t asb = (uint32_t)__cvta_generic_to_shared(As);
    uint32_t bsb = (uint32_t)__cvta_generic_to_shared(Bs);

    wmma::fragment<wmma::accumulator, 16, 16, 16, float> acc[4][2];
#pragma unroll
    for (int i = 0; i < 4; i++)
#pragma unroll
        for (int j = 0; j < 2; j++) wmma::fill_fragment(acc[i][j], 0.f);

    auto ldst = [&](int s, int b) {
        int k0 = s * BK;
#pragma unroll
        for (int i = 0; i < 4; i++) {                 // A: 128 x 64
            int idx = tid + (i << 8);
            int row = idx >> 3, c = idx & 7;
            cp16(asb + b * ASTG + (uint32_t)(row * LDH + c * 8) * 2,
                 A + (size_t)(row < mrem ? row : 0) * HID + k0 + c * 8,
                 row < mrem ? 16 : 0);
        }
#pragma unroll
        for (int i = 0; i < 4; i++) {                 // B: 128 x 64
            int idx = tid + (i << 8);
            int row = idx >> 3, c = idx & 7;
            cp16f(bsb + b * BSTG + (uint32_t)(row * LDH + c * 8) * 2,
                  B + (size_t)(n0 + row) * HID + k0 + c * 8);
        }
        cp_commit();
    };

    auto compute = [&](int b) {
#pragma unroll
        for (int kk = 0; kk < 4; kk++) {
            wmma::fragment<wmma::matrix_a, 16, 16, 16, __half, wmma::row_major> af[4];
            wmma::fragment<wmma::matrix_b, 16, 16, 16, __half, wmma::col_major> bf[2];
#pragma unroll
            for (int i = 0; i < 4; i++)
                wmma::load_matrix_sync(af[i], &As[b * (ASTG / 2) + (wm * 64 + i * 16) * LDH + kk * 16], LDH);
#pragma unroll
            for (int j = 0; j < 2; j++)
                wmma::load_matrix_sync(bf[j], &Bs[b * (BSTG / 2) + (wn * 32 + j * 16) * LDH + kk * 16], LDH);
#pragma unroll
            for (int i = 0; i < 4; i++)
#pragma unroll
                for (int j = 0; j < 2; j++)
                    wmma::mma_sync(acc[i][j], af[i], bf[j], acc[i][j]);
        }
    };

    const int NS = HID / BK;   // 16
    ldst(0, 0); ldst(1, 1);
    for (int s = 0; s < NS; s++) {
        if (s + 1 < NS) cp_wait<1>(); else cp_wait<0>();
        __syncthreads();
        compute(s % 3);
        if (s + 2 < NS) ldst(s + 2, (s + 2) % 3);
    }
    __syncthreads();

    float* Cs = (float*)dsm;                         // 128 x LDC2
#pragma unroll
    for (int i = 0; i < 4; i++)
#pragma unroll
        for (int j = 0; j < 2; j++)
            wmma::store_matrix_sync(&Cs[(wm * 64 + i * 16) * LDC2 + wn * 32 + j * 16],
                                    acc[i][j], LDC2, wmma::mem_row_major);
    __syncthreads();
#pragma unroll
    for (int i = 0; i < 16; i++) {                   // 128 rows x 32 float4
        int idx = tid + (i << 8);
        int row = idx >> 5, c4 = idx & 31;
        if (m0 + row < cnt) {
            int slot = s_slot[row];
            float4 v = *(float4*)&Cs[row * LDC2 + c4 * 4];
            float* dst = (slot == 0) ? g_r0 : (slot == 1) ? g_r1 : out;
            *(float4*)(dst + (size_t)s_tok[row] * DIM + n0 + c4 * 4) = v;
        }
    }
}

__global__ void k_final(float* __restrict__ out) {
    size_t i = (size_t)blockIdx.x * blockDim.x + threadIdx.x;
    if (i < (size_t)T_ * DIM / 4) {
        float4 o = ((const float4*)out)[i];
        float4 a = ((const float4*)g_r0)[i];
        float4 b = ((const float4*)g_r1)[i];
        o.x += a.x + b.x; o.y += a.y + b.y; o.z += a.z + b.z; o.w += a.w + b.w;
        ((float4*)out)[i] = o;
    }
}

// ---------------------------------------------------------------------------
extern "C" void kernel_launch(void* const* d_in, const int* in_sizes, int n_in,
                              void* d_out, int out_size) {
    const float* x   = (const float*)d_in[0];
    const float* gw  = (const float*)d_in[1];
    const float* w1  = (const float*)d_in[2];
    const float* w2  = (const float*)d_in[3];
    const float* w3  = (const float*)d_in[4];
    const float* ws1 = (const float*)d_in[5];
    const float* ws2 = (const float*)d_in[6];
    const float* ws3 = (const float*)d_in[7];
    float* out = (float*)d_out;

    cudaFuncSetAttribute(k_gemm1, cudaFuncAttributeMaxDynamicSharedMemorySize, 110592);
    cudaFuncSetAttribute(k_gemm2, cudaFuncAttributeMaxDynamicSharedMemorySize, 110592);

    k_router<<<T_ / 8, 256>>>(x, gw);
    k_scan<<<1, 256>>>();
    k_fill<<<T_ / 256, 256>>>();
    k_cvt_all<<<(TOT4 / CVT_ILP + 255) / 256, 256>>>(x, w1, w3, w2, ws1, ws3, ws2);

    k_gemm1<<<dim3(32, HID / 64, NG), 256, 110592>>>();
    k_gemm2<<<dim3(32, DIM / 128, NG), 256, 110592>>>(out);
    k_final<<<(T_ * DIM / 4 + 255) / 256, 256>>>(out);
}

// round 15
// speedup vs baseline: 1.0351x; 1.0351x over previous
#include <cuda_runtime.h>
#include <cuda_fp16.h>
#include <mma.h>
#include <math.h>
#include <cstdint>

using namespace nvcuda;

#define T_    4096
#define DIM   2048
#define HID   1024
#define NE    8
#define NG    9
#define SHB   8192
#define NPAIR 12288

#define BK    64
#define LDH   72     // smem stride in halves (144B) for BK=64
#define ASTG  18432  // A stage bytes  (128*72*2)
#define BSTG  18432  // B stage bytes  (128*72*2)
#define LDC   68     // GEMM1 epilogue C stride (floats)
#define LDC2  132    // GEMM2 epilogue C stride (floats)

struct Pair { int tok; int slot; float score; int pad; };

__device__ int   g_fill[NE];
__device__ int   g_off[NG + 1];
__device__ int   g_cnt[NG];
__device__ __align__(16) Pair g_pairs[NPAIR];
__device__ int   g_topk_idx[T_][2];
__device__ float g_topk_sc[T_][2];

__device__ __align__(128) __half g_xh[(size_t)T_ * DIM];
__device__ __align__(128) __half c_w1h[(size_t)NE * HID * DIM];
__device__ __align__(128) __half c_w3h[(size_t)NE * HID * DIM];
__device__ __align__(128) __half c_w2h[(size_t)NE * DIM * HID];
__device__ __align__(128) __half c_ws1h[(size_t)HID * DIM];
__device__ __align__(128) __half c_ws3h[(size_t)HID * DIM];
__device__ __align__(128) __half c_ws2h[(size_t)DIM * HID];
__device__ __align__(128) __half g_hh[(size_t)NPAIR * HID];
__device__ __align__(128) float  g_r0[(size_t)T_ * DIM];
__device__ __align__(128) float  g_r1[(size_t)T_ * DIM];

// ---------------- helpers ----------------
__device__ __forceinline__ void cp16(uint32_t dst, const void* src, int sz) {
    asm volatile("cp.async.cg.shared.global [%0], [%1], 16, %2;\n" :: "r"(dst), "l"(src), "r"(sz));
}
__device__ __forceinline__ void cp16f(uint32_t dst, const void* src) {
    asm volatile("cp.async.cg.shared.global [%0], [%1], 16;\n" :: "r"(dst), "l"(src));
}
__device__ __forceinline__ void cp_commit() { asm volatile("cp.async.commit_group;\n"); }
template<int N> __device__ __forceinline__ void cp_wait() {
    asm volatile("cp.async.wait_group %0;\n" :: "n"(N));
}

// ---------------- small kernels ----------------
__global__ void k_router(const float* __restrict__ x, const float* __restrict__ gw) {
    int warp = (blockIdx.x * blockDim.x + threadIdx.x) >> 5;
    int lane = threadIdx.x & 31;
    if (warp >= T_) return;
    const float* xr = x + (size_t)warp * DIM;
    float acc[NE];
#pragma unroll
    for (int e = 0; e < NE; e++) acc[e] = 0.f;
    for (int k = lane; k < DIM; k += 32) {
        float xv = xr[k];
#pragma unroll
        for (int e = 0; e < NE; e++) acc[e] += xv * gw[e * DIM + k];
    }
#pragma unroll
    for (int e = 0; e < NE; e++)
#pragma unroll
        for (int o = 16; o > 0; o >>= 1) acc[e] += __shfl_xor_sync(0xffffffffu, acc[e], o);
    if (lane == 0) {
        int i0 = 0; float v0 = acc[0];
#pragma unroll
        for (int e = 1; e < NE; e++) if (acc[e] > v0) { v0 = acc[e]; i0 = e; }
        int i1 = -1; float v1 = -1e30f;
#pragma unroll
        for (int e = 0; e < NE; e++) if (e != i0 && acc[e] > v1) { v1 = acc[e]; i1 = e; }
        g_topk_idx[warp][0] = i0; g_topk_idx[warp][1] = i1;
        g_topk_sc[warp][0] = 1.f / (1.f + expf(-v0));
        g_topk_sc[warp][1] = 1.f / (1.f + expf(-v1));
    }
}

// counts + offsets + zero g_fill
__global__ void k_scan() {
    __shared__ int sc[NE];
    int tid = threadIdx.x;
    if (tid < NE) sc[tid] = 0;
    __syncthreads();
    for (int t = tid; t < T_; t += 256) {
        atomicAdd(&sc[g_topk_idx[t][0]], 1);
        atomicAdd(&sc[g_topk_idx[t][1]], 1);
    }
    __syncthreads();
    if (tid == 0) {
        int o = 0;
        for (int e = 0; e < NE; e++) { g_off[e] = o; g_cnt[e] = sc[e]; o += sc[e]; }
        g_off[NE] = SHB; g_cnt[NE] = T_;
    }
    if (tid < NE) g_fill[tid] = 0;
}

__global__ void k_fill() {
    int t = blockIdx.x * blockDim.x + threadIdx.x;
    if (t >= T_) return;
#pragma unroll
    for (int k = 0; k < 2; k++) {
        int e = g_topk_idx[t][k];
        int pos = atomicAdd(&g_fill[e], 1);
        Pair p; p.tok = t; p.slot = k; p.score = g_topk_sc[t][k]; p.pad = 0;
        g_pairs[g_off[e] + pos] = p;
    }
    Pair ps; ps.tok = t; ps.slot = 2; ps.score = 1.f; ps.pad = 0;
    g_pairs[SHB + t] = ps;
}

// ---- single fused fp32->fp16 conversion (x + all 6 weights), ILP=4,
//      vectorized 16B stores (2x STG.128 per thread) ----
#define XF4    (T_ * DIM / 4)          // 2097152
#define BIG4   (NE * HID * DIM / 4)    // 4194304
#define SMALL4 (HID * DIM / 4)         // 524288
#define TOT4   (XF4 + 3 * BIG4 + 3 * SMALL4)   // 16252928
#define CVT_ILP 4

__global__ void k_cvt_all(const float* __restrict__ x,
                          const float* __restrict__ w1, const float* __restrict__ w3,
                          const float* __restrict__ w2, const float* __restrict__ ws1,
                          const float* __restrict__ ws3, const float* __restrict__ ws2) {
    long long base = ((long long)blockIdx.x * blockDim.x + threadIdx.x) * CVT_ILP;
    if (base >= (long long)TOT4) return;
    const float* src; __half* dst; long long o;
    long long b = base;
    if      (b < (long long)XF4)                       { src = x;   dst = g_xh;   o = b; }
    else if ((b -= XF4) < (long long)BIG4)             { src = w1;  dst = c_w1h;  o = b; }
    else if ((b -= BIG4) < (long long)BIG4)            { src = w3;  dst = c_w3h;  o = b; }
    else if ((b -= BIG4) < (long long)BIG4)            { src = w2;  dst = c_w2h;  o = b; }
    else if ((b -= BIG4) < (long long)SMALL4)          { src = ws1; dst = c_ws1h; o = b; }
    else if ((b -= SMALL4) < (long long)SMALL4)        { src = ws3; dst = c_ws3h; o = b; }
    else                                               { src = ws2; dst = c_ws2h; o = b - SMALL4; }
    float4 v[CVT_ILP];
#pragma unroll
    for (int j = 0; j < CVT_ILP; j++) v[j] = ((const float4*)src)[o + j];
    uint4 s[2];
#pragma unroll
    for (int j = 0; j < 2; j++) {
        __half2 h0 = __floats2half2_rn(v[2*j].x,   v[2*j].y);
        __half2 h1 = __floats2half2_rn(v[2*j].z,   v[2*j].w);
        __half2 h2 = __floats2half2_rn(v[2*j+1].x, v[2*j+1].y);
        __half2 h3 = __floats2half2_rn(v[2*j+1].z, v[2*j+1].w);
        s[j].x = *(uint32_t*)&h0; s[j].y = *(uint32_t*)&h1;
        s[j].z = *(uint32_t*)&h2; s[j].w = *(uint32_t*)&h3;
    }
    uint4* d4 = (uint4*)dst + (o >> 1);   // o multiple of 4 -> exact
    d4[0] = s[0];
    d4[1] = s[1];
}

// ---------------------------------------------------------------------------
// GEMM1: fp16 wmma, M=128, concat N=128 (64 w1 + 64 w3), BK=64.
// 8 warps 2x4; warp tile 64x32. 3-stage ring, 1 sync/stage (R10 order).
// ---------------------------------------------------------------------------
__global__ void __launch_bounds__(256, 2) k_gemm1() {
    int g = blockIdx.z;
    int cnt = g_cnt[g];
    int m0 = blockIdx.x * 128;
    if (m0 >= cnt) return;
    int off = g_off[g];
    int n0 = blockIdx.y * 64;
    const __half* B1 = (g < NE) ? c_w1h + (size_t)g * HID * DIM : c_ws1h;
    const __half* B3 = (g < NE) ? c_w3h + (size_t)g * HID * DIM : c_ws3h;

    extern __shared__ __align__(16) char dsm[];
    __half* As = (__half*)dsm;                 // 3 * 18432 B
    __half* Bs = (__half*)(dsm + 3 * ASTG);    // 3 * 18432 B
    __shared__ int   s_tok[128];
    __shared__ float s_sc[128];

    int tid = threadIdx.x, warp = tid >> 5;
    int wm = warp >> 2, wn = warp & 3;
    if (tid < 128) {
        int mi = m0 + tid;
        if (mi < cnt) { Pair p = g_pairs[off + mi]; s_tok[tid] = p.tok; s_sc[tid] = p.score; }
        else          { s_tok[tid] = -1; s_sc[tid] = 0.f; }
    }
    __syncthreads();

    uint32_t asb = (uint32_t)__cvta_generic_to_shared(As);
    uint32_t bsb = (uint32_t)__cvta_generic_to_shared(Bs);

    wmma::fragment<wmma::accumulator, 16, 16, 16, float> acc[4][2];
#pragma unroll
    for (int i = 0; i < 4; i++)
#pragma unroll
        for (int j = 0; j < 2; j++) wmma::fill_fragment(acc[i][j], 0.f);

    auto ldst = [&](int s, int b) {
        int k0 = s * BK;
#pragma unroll
        for (int i = 0; i < 4; i++) {                 // A: 128 rows x 8 chunks
            int idx = tid + (i << 8);
            int row = idx >> 3, c = idx & 7;
            int tok = s_tok[row];
            cp16(asb + b * ASTG + (uint32_t)(row * LDH + c * 8) * 2,
                 g_xh + (size_t)(tok < 0 ? 0 : tok) * DIM + k0 + c * 8,
                 tok < 0 ? 0 : 16);
        }
#pragma unroll
        for (int i = 0; i < 4; i++) {                 // B concat: rows 0-63 w1, 64-127 w3
            int idx = tid + (i << 8);
            int row = idx >> 3, c = idx & 7;
            const __half* src = (row < 64)
                ? B1 + (size_t)(n0 + row) * DIM + k0 + c * 8
                : B3 + (size_t)(n0 + row - 64) * DIM + k0 + c * 8;
            cp16f(bsb + b * BSTG + (uint32_t)(row * LDH + c * 8) * 2, src);
        }
        cp_commit();
    };

    auto compute = [&](int b) {
#pragma unroll
        for (int kk = 0; kk < 4; kk++) {
            wmma::fragment<wmma::matrix_a, 16, 16, 16, __half, wmma::row_major> af[4];
            wmma::fragment<wmma::matrix_b, 16, 16, 16, __half, wmma::col_major> bf[2];
#pragma unroll
            for (int i = 0; i < 4; i++)
                wmma::load_matrix_sync(af[i], &As[b * (ASTG / 2) + (wm * 64 + i * 16) * LDH + kk * 16], LDH);
#pragma unroll
            for (int j = 0; j < 2; j++)
                wmma::load_matrix_sync(bf[j], &Bs[b * (BSTG / 2) + (wn * 32 + j * 16) * LDH + kk * 16], LDH);
#pragma unroll
            for (int i = 0; i < 4; i++)
#pragma unroll
                for (int j = 0; j < 2; j++)
                    wmma::mma_sync(acc[i][j], af[i], bf[j], acc[i][j]);
        }
    };

    const int NS = DIM / BK;   // 32
    ldst(0, 0); ldst(1, 1);
    for (int s = 0; s < NS; s++) {
        if (s + 1 < NS) cp_wait<1>(); else cp_wait<0>();
        __syncthreads();
        compute(s % 3);
        if (s + 2 < NS) ldst(s + 2, (s + 2) % 3);
    }
    __syncthreads();   // pipeline smem quiesced before epilogue reuse

    // epilogue: C1 (p1) / C3 (p3) to smem, SwiGLU + score, store half
    float* C1 = (float*)dsm;
    float* C3 = (float*)dsm + 128 * LDC;
    float* Cd = (wn < 2) ? C1 : C3;
    int cc = (wn & 1) * 32;
#pragma unroll
    for (int i = 0; i < 4; i++)
#pragma unroll
        for (int j = 0; j < 2; j++)
            wmma::store_matrix_sync(&Cd[(wm * 64 + i * 16) * LDC + cc + j * 16],
                                    acc[i][j], LDC, wmma::mem_row_major);
    __syncthreads();
#pragma unroll
    for (int i = 0; i < 8; i++) {                    // 128 rows x 16 float4
        int idx = tid + (i << 8);
        int row = idx >> 4, c4 = idx & 15;
        if (m0 + row < cnt) {
            float sc = s_sc[row];
            float4 v1 = *(float4*)&C1[row * LDC + c4 * 4];
            float4 v3 = *(float4*)&C3[row * LDC + c4 * 4];
            float o0, o1, o2, o3, p1, p3;
            p1 = v1.x * sc; p3 = v3.x * sc; o0 = p1 * (1.f / (1.f + __expf(-p1))) * p3;
            p1 = v1.y * sc; p3 = v3.y * sc; o1 = p1 * (1.f / (1.f + __expf(-p1))) * p3;
            p1 = v1.z * sc; p3 = v3.z * sc; o2 = p1 * (1.f / (1.f + __expf(-p1))) * p3;
            p1 = v1.w * sc; p3 = v3.w * sc; o3 = p1 * (1.f / (1.f + __expf(-p1))) * p3;
            __half* hdst = g_hh + (size_t)(off + m0 + row) * HID + n0 + c4 * 4;
            *(__half2*)(hdst)     = __floats2half2_rn(o0, o1);
            *(__half2*)(hdst + 2) = __floats2half2_rn(o2, o3);
        }
    }
}

// ---------------------------------------------------------------------------
// GEMM2: fp16 wmma, M=128, N=128, K=HID, BK=64. 3-stage ring (R10 order).
// All 9 groups in one grid; slot0->g_r0, slot1->g_r1, shared->out.
// ---------------------------------------------------------------------------
__global__ void __launch_bounds__(256, 2) k_gemm2(float* __restrict__ out) {
    int g = blockIdx.z;
    int cnt = g_cnt[g];
    int m0 = blockIdx.x * 128;
    if (m0 >= cnt) return;
    int off = g_off[g];
    int n0 = blockIdx.y * 128;
    const __half* B = (g < NE) ? c_w2h + (size_t)g * DIM * HID : c_ws2h;
    const __half* A = g_hh + (size_t)(off + m0) * HID;
    int mrem = cnt - m0;

    extern __shared__ __align__(16) char dsm[];
    __half* As = (__half*)dsm;                 // 3 * 18432 B
    __half* Bs = (__half*)(dsm + 3 * ASTG);    // 3 * 18432 B
    __shared__ int s_tok[128];
    __shared__ int s_slot[128];

    int tid = threadIdx.x, warp = tid >> 5;
    int wm = warp >> 2, wn = warp & 3;
    if (tid < 128) {
        int mi = m0 + tid;
        if (mi < cnt) { Pair p = g_pairs[off + mi]; s_tok[tid] = p.tok; s_slot[tid] = p.slot; }
        else          { s_tok[tid] = 0; s_slot[tid] = -1; }
    }
    __syncthreads();

    uint32_t asb = (uint32_t)__cvta_generic_to_shared(As);
    uint32_t bsb = (uint32_t)__cvta_generic_to_shared(Bs);

    wmma::fragment<wmma::accumulator, 16, 16, 16, float> acc[4][2];
#pragma unroll
    for (int i = 0; i < 4; i++)
#pragma unroll
        for (int j = 0; j < 2; j++) wmma::fill_fragment(acc[i][j], 0.f);

    auto ldst = [&](int s, int b) {
        int k0 = s * BK;
#pragma unroll
        for (int i = 0; i < 4; i++) {                 // A: 128 x 64
            int idx = tid + (i << 8);
            int row = idx >> 3, c = idx & 7;
            cp16(asb + b * ASTG + (uint32_t)(row * LDH + c * 8) * 2,
                 A + (size_t)(row < mrem ? row : 0) * HID + k0 + c * 8,
                 row < mrem ? 16 : 0);
        }
#pragma unroll
        for (int i = 0; i < 4; i++) {                 // B: 128 x 64
            int idx = tid + (i << 8);
            int row = idx >> 3, c = idx & 7;
            cp16f(bsb + b * BSTG + (uint32_t)(row * LDH + c * 8) * 2,
                  B + (size_t)(n0 + row) * HID + k0 + c * 8);
        }
        cp_commit();
    };

    auto compute = [&](int b) {
#pragma unroll
        for (int kk = 0; kk < 4; kk++) {
            wmma::fragment<wmma::matrix_a, 16, 16, 16, __half, wmma::row_major> af[4];
            wmma::fragment<wmma::matrix_b, 16, 16, 16, __half, wmma::col_major> bf[2];
#pragma unroll
            for (int i = 0; i < 4; i++)
                wmma::load_matrix_sync(af[i], &As[b * (ASTG / 2) + (wm * 64 + i * 16) * LDH + kk * 16], LDH);
#pragma unroll
            for (int j = 0; j < 2; j++)
                wmma::load_matrix_sync(bf[j], &Bs[b * (BSTG / 2) + (wn * 32 + j * 16) * LDH + kk * 16], LDH);
#pragma unroll
            for (int i = 0; i < 4; i++)
#pragma unroll
                for (int j = 0; j < 2; j++)
                    wmma::mma_sync(acc[i][j], af[i], bf[j], acc[i][j]);
        }
    };

    const int NS = HID / BK;   // 16
    ldst(0, 0); ldst(1, 1);
    for (int s = 0; s < NS; s++) {
        if (s + 1 < NS) cp_wait<1>(); else cp_wait<0>();
        __syncthreads();
        compute(s % 3);
        if (s + 2 < NS) ldst(s + 2, (s + 2) % 3);
    }
    __syncthreads();

    float* Cs = (float*)dsm;                         // 128 x LDC2
#pragma unroll
    for (int i = 0; i < 4; i++)
#pragma unroll
        for (int j = 0; j < 2; j++)
            wmma::store_matrix_sync(&Cs[(wm * 64 + i * 16) * LDC2 + wn * 32 + j * 16],
                                    acc[i][j], LDC2, wmma::mem_row_major);
    __syncthreads();
#pragma unroll
    for (int i = 0; i < 16; i++) {                   // 128 rows x 32 float4
        int idx = tid + (i << 8);
        int row = idx >> 5, c4 = idx & 31;
        if (m0 + row < cnt) {
            int slot = s_slot[row];
            float4 v = *(float4*)&Cs[row * LDC2 + c4 * 4];
            float* dst = (slot == 0) ? g_r0 : (slot == 1) ? g_r1 : out;
            *(float4*)(dst + (size_t)s_tok[row] * DIM + n0 + c4 * 4) = v;
        }
    }
}

__global__ void k_final(float* __restrict__ out) {
    size_t i = (size_t)blockIdx.x * blockDim.x + threadIdx.x;
    if (i < (size_t)T_ * DIM / 4) {
        float4 o = ((const float4*)out)[i];
        float4 a = ((const float4*)g_r0)[i];
        float4 b = ((const float4*)g_r1)[i];
        o.x += a.x + b.x; o.y += a.y + b.y; o.z += a.z + b.z; o.w += a.w + b.w;
        ((float4*)out)[i] = o;
    }
}

// ---------------------------------------------------------------------------
extern "C" void kernel_launch(void* const* d_in, const int* in_sizes, int n_in,
                              void* d_out, int out_size) {
    const float* x   = (const float*)d_in[0];
    const float* gw  = (const float*)d_in[1];
    const float* w1  = (const float*)d_in[2];
    const float* w2  = (const float*)d_in[3];
    const float* w3  = (const float*)d_in[4];
    const float* ws1 = (const float*)d_in[5];
    const float* ws2 = (const float*)d_in[6];
    const float* ws3 = (const float*)d_in[7];
    float* out = (float*)d_out;

    cudaFuncSetAttribute(k_gemm1, cudaFuncAttributeMaxDynamicSharedMemorySize, 110592);
    cudaFuncSetAttribute(k_gemm2, cudaFuncAttributeMaxDynamicSharedMemorySize, 110592);

    k_router<<<T_ / 8, 256>>>(x, gw);
    k_scan<<<1, 256>>>();
    k_fill<<<T_ / 256, 256>>>();
    k_cvt_all<<<(TOT4 / CVT_ILP + 255) / 256, 256>>>(x, w1, w3, w2, ws1, ws3, ws2);

    k_gemm1<<<dim3(32, HID / 64, NG), 256, 110592>>>();
    k_gemm2<<<dim3(32, DIM / 128, NG), 256, 110592>>>(out);
    k_final<<<(T_ * DIM / 4 + 255) / 256, 256>>>(out);
}